// round 1
// baseline (speedup 1.0000x reference)
#include <cuda_runtime.h>
#include <math.h>

#define FF 15
#define HH 128
#define LL 12
#define NBINS 16
#define MM 47          // 3*NB - 1
#define OUTW (FF*MM)   // 705
#define TAILV 3.0f
#define MINW 0.001f
#define MINH 0.001f
#define MIND 0.001f
#define SPB 128        // samples per block
#define TL 132         // row stride for h/t buffers (128 + 4 pad)
#define XL 16          // row stride for x buffer

// Pre-masked, transposed weights (scratch; __device__ globals are allowed)
__device__ float g_Wi[LL * 16 * HH];        // [l][k(=feature,16 pad)][j]
__device__ float g_Wr[LL * 4 * HH * HH];    // [l][blk*2+sub][k][j]
__device__ float g_Wo[LL * HH * OUTW];      // [l][k][o]

// ---------------------------------------------------------------------------
// Prep: apply autoregressive masks and transpose weights for coalesced reads.
// deg_h[j] = j % 14 + 1 ; deg_in[f] = f+1 ; deg_out[o] = o/47 + 1
// ---------------------------------------------------------------------------
__global__ void prep_kernel(const float* __restrict__ Wi,
                            const float* __restrict__ Wr,
                            const float* __restrict__ Wo)
{
    const int n1 = LL * 16 * HH;
    const int n2 = LL * 4 * HH * HH;
    const int n3 = LL * HH * OUTW;
    for (int i = blockIdx.x * blockDim.x + threadIdx.x; i < n1 + n2 + n3;
         i += gridDim.x * blockDim.x) {
        if (i < n1) {
            int j = i % HH;
            int k = (i / HH) % 16;
            int l = i / (16 * HH);
            float v = 0.f;
            if (k < FF) {
                int degh = j % (FF - 1) + 1;
                if (degh >= k + 1) v = Wi[(l * HH + j) * FF + k];
            }
            g_Wi[i] = v;
        } else if (i < n1 + n2) {
            int t = i - n1;
            int j = t % HH;               // output index
            int k = (t / HH) % HH;        // input index
            int m = t / (HH * HH);        // l*4 + blk*2 + sub
            int degj = j % (FF - 1) + 1;
            int degk = k % (FF - 1) + 1;
            g_Wr[t] = (degj >= degk) ? Wr[(m * HH + j) * HH + k] : 0.f;
        } else {
            int t = i - n1 - n2;
            int o = t % OUTW;
            int k = (t / OUTW) % HH;
            int l = t / (HH * OUTW);
            int dego = o / MM + 1;
            int degk = k % (FF - 1) + 1;
            g_Wo[t] = (dego > degk) ? Wo[(l * OUTW + o) * HH + k] : 0.f;
        }
    }
}

// ---------------------------------------------------------------------------
// Register-tiled SMEM GEMM: C[128 x N] (+)= op(A[128 x K]) @ W[K x N] + bias
//   A in smem (row stride ald), W in global (row stride wld), C in smem.
//   256 threads = 16(ty, rows of 8) x 16(tx, cols of NC). col = tx*NC + j.
// ---------------------------------------------------------------------------
template <int K, int N, int NC, bool RELU, bool ACC>
__device__ __forceinline__ void gemm(const float* __restrict__ As, int ald,
                                     const float* __restrict__ Wg, int wld,
                                     const float* __restrict__ bias,
                                     float* __restrict__ Cs, int cld,
                                     int tx, int ty)
{
    float acc[8][NC];
#pragma unroll
    for (int j = 0; j < NC; j++) {
        int c = tx * NC + j;
        float b = (c < N) ? __ldg(&bias[c]) : 0.f;
#pragma unroll
        for (int i = 0; i < 8; i++) {
            int r = ty * 8 + i;
            float prev = 0.f;
            if (ACC && c < N) prev = Cs[r * cld + c];
            acc[i][j] = b + prev;
        }
    }

#pragma unroll 1
    for (int k0 = 0; k0 < K; k0 += 4) {
        float4 a[8];
#pragma unroll
        for (int i = 0; i < 8; i++) {
            a[i] = *(const float4*)&As[(ty * 8 + i) * ald + k0];
            if (RELU) {
                a[i].x = fmaxf(a[i].x, 0.f);
                a[i].y = fmaxf(a[i].y, 0.f);
                a[i].z = fmaxf(a[i].z, 0.f);
                a[i].w = fmaxf(a[i].w, 0.f);
            }
        }
#pragma unroll
        for (int kk = 0; kk < 4; kk++) {
            float w[NC];
#pragma unroll
            for (int j = 0; j < NC; j++) {
                int c = tx * NC + j;
                w[j] = (c < N) ? __ldg(&Wg[(k0 + kk) * wld + c]) : 0.f;
            }
#pragma unroll
            for (int i = 0; i < 8; i++) {
                float av = (kk == 0) ? a[i].x : (kk == 1) ? a[i].y
                         : (kk == 2) ? a[i].z : a[i].w;
#pragma unroll
                for (int j = 0; j < NC; j++)
                    acc[i][j] = fmaf(av, w[j], acc[i][j]);
            }
        }
    }

#pragma unroll
    for (int i = 0; i < 8; i++) {
        int r = ty * 8 + i;
#pragma unroll
        for (int j = 0; j < NC; j++) {
            int c = tx * NC + j;
            if (c < N) Cs[r * cld + c] = acc[i][j];
        }
    }
}

__device__ __forceinline__ float softplusf(float v)
{
    return (v > 15.f) ? v : log1pf(__expf(v));
}

// ---------------------------------------------------------------------------
// Rational-quadratic spline for one (sample, feature).
// trow: 47 raw params at [0..46]; scratch cw at [48..64], ch at [66..82].
// ---------------------------------------------------------------------------
__device__ void rqs_transform(float* __restrict__ trow,
                              float* __restrict__ xrow,
                              float* __restrict__ ldp, int f)
{
    float x = xrow[f];
    bool inside = (x >= -TAILV) && (x <= TAILV);
    float xc = fminf(fmaxf(x, -TAILV), TAILV);

    // widths softmax -> knot positions cw[0..16]
    {
        float mw = trow[0];
#pragma unroll
        for (int i = 1; i < NBINS; i++) mw = fmaxf(mw, trow[i]);
        float e[NBINS]; float S = 0.f;
#pragma unroll
        for (int i = 0; i < NBINS; i++) { e[i] = __expf(trow[i] - mw); S += e[i]; }
        float sc = (1.f - MINW * NBINS) / S;
        trow[48] = -TAILV;
        float c = 0.f;
#pragma unroll
        for (int i = 0; i < NBINS; i++) {
            c += MINW + sc * e[i];
            trow[49 + i] = 6.f * c - 3.f;
        }
        trow[48 + NBINS] = TAILV;  // force endpoint
    }
    // heights softmax -> knot positions ch[0..16]
    {
        float mh = trow[16];
#pragma unroll
        for (int i = 1; i < NBINS; i++) mh = fmaxf(mh, trow[16 + i]);
        float e[NBINS]; float S = 0.f;
#pragma unroll
        for (int i = 0; i < NBINS; i++) { e[i] = __expf(trow[16 + i] - mh); S += e[i]; }
        float sc = (1.f - MINH * NBINS) / S;
        trow[66] = -TAILV;
        float c = 0.f;
#pragma unroll
        for (int i = 0; i < NBINS; i++) {
            c += MINH + sc * e[i];
            trow[67 + i] = 6.f * c - 3.f;
        }
        trow[66 + NBINS] = TAILV;
    }

    int idx = 0;
#pragma unroll
    for (int i = 1; i <= 15; i++) idx += (xc >= trow[48 + i]) ? 1 : 0;

    float cwlo = trow[48 + idx], cwhi = trow[49 + idx];
    float chlo = trow[66 + idx], chhi = trow[67 + idx];
    float inw = cwhi - cwlo;
    float inh = chhi - chlo;
    float delta = inh / inw;
    float ind  = (idx == 0)  ? 1.f : MIND + softplusf(trow[32 + idx - 1]);
    float ind1 = (idx == 15) ? 1.f : MIND + softplusf(trow[32 + idx]);

    float th   = (xc - cwlo) / inw;
    float omt  = 1.f - th;
    float tomt = th * omt;
    float num  = inh * (delta * th * th + ind * tomt);
    float den  = delta + (ind + ind1 - 2.f * delta) * tomt;
    float y    = chlo + num / den;
    float dnum = delta * delta * (ind1 * th * th + 2.f * delta * tomt + ind * omt * omt);
    float lad  = __logf(dnum) - 2.f * __logf(den);

    xrow[f] = inside ? y : x;
    *ldp += inside ? lad : 0.f;
}

// ---------------------------------------------------------------------------
// Fused flow kernel: one CTA carries 128 samples through all 12 layers.
// ---------------------------------------------------------------------------
__global__ void __launch_bounds__(256, 1)
flow_kernel(const float* __restrict__ x_in,
            const float* __restrict__ b_init,
            const float* __restrict__ b_res,
            const float* __restrict__ b_out,
            float* __restrict__ out, int batch)
{
    extern __shared__ float sm[];
    float* xs   = sm;                      // SPB * XL
    float* hbuf = xs + SPB * XL;           // SPB * TL
    float* tbuf = hbuf + SPB * TL;         // SPB * TL
    float* ldv  = tbuf + SPB * TL;         // SPB

    int tid = threadIdx.x;
    int tx = tid & 15, ty = tid >> 4;
    int base = blockIdx.x * SPB;

    // load x tile (+ zero pad column, zero logdet)
    for (int i = tid; i < SPB * FF; i += 256) {
        int s = i / FF, f = i % FF;
        xs[s * XL + f] = x_in[(base + s) * FF + f];
    }
    for (int i = tid; i < SPB; i += 256) { xs[i * XL + FF] = 0.f; ldv[i] = 0.f; }
    __syncthreads();

    for (int l = 0; l < LL; l++) {
        // feature reversal (thread s owns its whole row: no cross-thread hazard)
        if (tid < SPB) {
            float v[FF];
#pragma unroll
            for (int f = 0; f < FF; f++) v[f] = xs[tid * XL + f];
#pragma unroll
            for (int f = 0; f < FF; f++) xs[tid * XL + f] = v[FF - 1 - f];
        }
        __syncthreads();

        // h = xs @ Wi^T + bi
        gemm<16, 128, 8, false, false>(xs, XL, g_Wi + l * 16 * HH, HH,
                                       b_init + l * HH, hbuf, TL, tx, ty);
        __syncthreads();

        const float* wr = g_Wr + l * 4 * HH * HH;
        const float* br = b_res + l * 4 * HH;

        // block 0
        gemm<128, 128, 8, true, false>(hbuf, TL, wr, HH, br, tbuf, TL, tx, ty);
        __syncthreads();
        gemm<128, 128, 8, true, true>(tbuf, TL, wr + HH * HH, HH, br + HH,
                                      hbuf, TL, tx, ty);
        __syncthreads();
        // block 1
        gemm<128, 128, 8, true, false>(hbuf, TL, wr + 2 * HH * HH, HH,
                                       br + 2 * HH, tbuf, TL, tx, ty);
        __syncthreads();
        gemm<128, 128, 8, true, true>(tbuf, TL, wr + 3 * HH * HH, HH,
                                      br + 3 * HH, hbuf, TL, tx, ty);
        __syncthreads();

        // output head in 15 per-feature chunks of 47, each fused with RQS
        for (int f = 0; f < FF; f++) {
            gemm<128, 47, 3, false, false>(hbuf, TL,
                                           g_Wo + l * HH * OUTW + f * MM, OUTW,
                                           b_out + l * OUTW + f * MM,
                                           tbuf, TL, tx, ty);
            __syncthreads();
            if (tid < SPB)
                rqs_transform(&tbuf[tid * TL], &xs[tid * XL], &ldv[tid], f);
            __syncthreads();
        }
    }

    // write z then logdet
    for (int i = tid; i < SPB * FF; i += 256) {
        int s = i / FF, f = i % FF;
        out[(base + s) * FF + f] = xs[s * XL + f];
    }
    if (tid < SPB) out[batch * FF + base + tid] = ldv[tid];
}

static const int SMEM_BYTES = (SPB * XL + 2 * SPB * TL + SPB) * (int)sizeof(float);

extern "C" void kernel_launch(void* const* d_in, const int* in_sizes, int n_in,
                              void* d_out, int out_size)
{
    const float* x  = (const float*)d_in[0];
    const float* Wi = (const float*)d_in[1];
    const float* bi = (const float*)d_in[2];
    const float* Wr = (const float*)d_in[3];
    const float* br = (const float*)d_in[4];
    const float* Wo = (const float*)d_in[5];
    const float* bo = (const float*)d_in[6];
    float* out = (float*)d_out;

    int batch = in_sizes[0] / FF;

    cudaFuncSetAttribute(flow_kernel,
                         cudaFuncAttributeMaxDynamicSharedMemorySize, SMEM_BYTES);

    prep_kernel<<<2048, 256>>>(Wi, Wr, Wo);
    flow_kernel<<<batch / SPB, 256, SMEM_BYTES>>>(x, bi, br, bo, out, batch);
}

// round 2
// speedup vs baseline: 1.1728x; 1.1728x over previous
#include <cuda_runtime.h>
#include <math.h>

#define FF 15
#define HH 128
#define LL 12
#define NBINS 16
#define MM 47            // 3*NB - 1
#define OUTW (FF*MM)     // 705
#define FP 48            // padded per-feature width
#define NFP 16           // padded feature count
#define OUTWP (NFP*FP)   // 768
#define TAILV 3.0f
#define MINW 0.001f
#define MINH 0.001f
#define MIND 0.001f
#define SPB 128          // samples per block
#define TL 132           // row stride for h/t buffers
#define XL 16            // row stride for x buffer
#define NT 512           // threads per CTA

typedef unsigned long long ull;

// Pre-masked, transposed, padded weights (scratch)
__device__ float g_Wi[LL * 16 * HH];        // [l][k(16)][j]
__device__ float g_Wr[LL * 4 * HH * HH];    // [l][blk*2+sub][k][j]
__device__ float g_Wo[LL * HH * OUTWP];     // [l][k][f*48+m]
__device__ float g_bo[LL * OUTWP];          // padded out bias

// ---------------------------------------------------------------------------
__global__ void prep_kernel(const float* __restrict__ Wi,
                            const float* __restrict__ Wr,
                            const float* __restrict__ Wo,
                            const float* __restrict__ bo)
{
    const int n1 = LL * 16 * HH;
    const int n2 = LL * 4 * HH * HH;
    const int n3 = LL * HH * OUTWP;
    const int n4 = LL * OUTWP;
    for (int i = blockIdx.x * blockDim.x + threadIdx.x; i < n1 + n2 + n3 + n4;
         i += gridDim.x * blockDim.x) {
        if (i < n1) {
            int j = i % HH;
            int k = (i / HH) % 16;
            int l = i / (16 * HH);
            float v = 0.f;
            if (k < FF) {
                int degh = j % (FF - 1) + 1;
                if (degh >= k + 1) v = Wi[(l * HH + j) * FF + k];
            }
            g_Wi[i] = v;
        } else if (i < n1 + n2) {
            int t = i - n1;
            int j = t % HH;
            int k = (t / HH) % HH;
            int m = t / (HH * HH);
            int degj = j % (FF - 1) + 1;
            int degk = k % (FF - 1) + 1;
            g_Wr[t] = (degj >= degk) ? Wr[(m * HH + j) * HH + k] : 0.f;
        } else if (i < n1 + n2 + n3) {
            int t = i - n1 - n2;
            int c = t % OUTWP;              // f*48+m
            int k = (t / OUTWP) % HH;
            int l = t / (HH * OUTWP);
            int f = c / FP, m = c % FP;
            float v = 0.f;
            if (f < FF && m < MM) {
                int degk = k % (FF - 1) + 1;
                if (f + 1 > degk) v = Wo[(l * OUTW + f * MM + m) * HH + k];
            }
            g_Wo[t] = v;
        } else {
            int t = i - n1 - n2 - n3;
            int c = t % OUTWP;
            int l = t / OUTWP;
            int f = c / FP, m = c % FP;
            g_bo[t] = (f < FF && m < MM) ? bo[l * OUTW + f * MM + m] : 0.f;
        }
    }
}

// ---------------------------------------------------------------------------
__device__ __forceinline__ void fma2(ull& d, ull a, ull b)
{
    asm("fma.rn.f32x2 %0, %1, %2, %0;" : "+l"(d) : "l"(a), "l"(b));
}
__device__ __forceinline__ ull pack2(float v)
{
    ull r; asm("mov.b64 %0, {%1, %1};" : "=l"(r) : "f"(v)); return r;
}
__device__ __forceinline__ ull packf2(float a, float b)
{
    ull r; asm("mov.b64 %0, {%1, %2};" : "=l"(r) : "f"(a), "f"(b)); return r;
}

// ---------------------------------------------------------------------------
// Packed-f32x2 register-tiled GEMM: C[128 x N] (+)= op(A[128 x K]) @ W[K x N] + b
// 512 threads: ty = tid>>4 (0..31) -> 4 rows each; tx = tid&15 -> NC cols.
// N must equal 16*NC; NC even; bias must be readable for all N cols.
// ---------------------------------------------------------------------------
template <int K, int NC, bool RELU, bool ACC>
__device__ __forceinline__ void gemm2(const float* __restrict__ As, int ald,
                                      const float* __restrict__ Wg, int wld,
                                      const float* __restrict__ bias,
                                      float* __restrict__ Cs, int cld,
                                      int tx, int ty)
{
    constexpr int NP = NC / 2;
    const int c0 = tx * NC;
    const int r0 = ty * 4;

    ull acc[4][NP];
#pragma unroll
    for (int j = 0; j < NP; j++) {
        float2 b = *(const float2*)&bias[c0 + 2 * j];
#pragma unroll
        for (int i = 0; i < 4; i++) {
            float2 p = make_float2(0.f, 0.f);
            if (ACC) p = *(const float2*)&Cs[(r0 + i) * cld + c0 + 2 * j];
            acc[i][j] = packf2(b.x + p.x, b.y + p.y);
        }
    }

#pragma unroll 1
    for (int k0 = 0; k0 < K; k0 += 4) {
        float4 a[4];
#pragma unroll
        for (int i = 0; i < 4; i++) {
            a[i] = *(const float4*)&As[(r0 + i) * ald + k0];
            if (RELU) {
                a[i].x = fmaxf(a[i].x, 0.f);
                a[i].y = fmaxf(a[i].y, 0.f);
                a[i].z = fmaxf(a[i].z, 0.f);
                a[i].w = fmaxf(a[i].w, 0.f);
            }
        }
        ull w[4][NP];
#pragma unroll
        for (int kk = 0; kk < 4; kk++) {
            const float* wr = &Wg[(k0 + kk) * wld + c0];
#pragma unroll
            for (int j = 0; j < NP; j++)
                w[kk][j] = __ldg((const ull*)(wr + 2 * j));
        }
#pragma unroll
        for (int kk = 0; kk < 4; kk++) {
#pragma unroll
            for (int i = 0; i < 4; i++) {
                float av = (kk == 0) ? a[i].x : (kk == 1) ? a[i].y
                         : (kk == 2) ? a[i].z : a[i].w;
                ull av2 = pack2(av);
#pragma unroll
                for (int j = 0; j < NP; j++)
                    fma2(acc[i][j], av2, w[kk][j]);
            }
        }
    }

#pragma unroll
    for (int i = 0; i < 4; i++)
#pragma unroll
        for (int j = 0; j < NP; j++)
            *(float2*)&Cs[(r0 + i) * cld + c0 + 2 * j] = *(float2*)&acc[i][j];
}

// ---------------------------------------------------------------------------
__device__ __forceinline__ float softplusf(float v)
{
    return (v > 15.f) ? v : log1pf(__expf(v));
}

// Rational-quadratic spline, register-only scratch. p = 47 raw params (smem).
__device__ void rqs_reg(const float* __restrict__ p,
                        float* __restrict__ xp, float* __restrict__ ldp)
{
    float x = *xp;
    bool inside = (x >= -TAILV) && (x <= TAILV);
    float xc = fminf(fmaxf(x, -TAILV), TAILV);

    // widths softmax
    float ew[NBINS], eh[NBINS];
    float mw = p[0], mh = p[16];
#pragma unroll
    for (int i = 1; i < NBINS; i++) { mw = fmaxf(mw, p[i]); mh = fmaxf(mh, p[16 + i]); }
    float Sw = 0.f, Sh = 0.f;
#pragma unroll
    for (int i = 0; i < NBINS; i++) {
        ew[i] = __expf(p[i] - mw);      Sw += ew[i];
        eh[i] = __expf(p[16 + i] - mh); Sh += eh[i];
    }
    float scw = (1.f - MINW * NBINS) / Sw;
    float sch = (1.f - MINH * NBINS) / Sh;

    // single-pass width-knot search: idx, cw[idx], cw[idx+1]
    int idx = 0;
    float cwlo = -TAILV, cwhi = TAILV;
    bool found = false;
    float cacc = 0.f;
#pragma unroll
    for (int i = 0; i < NBINS - 1; i++) {
        cacc += MINW + scw * ew[i];
        float cw = 6.f * cacc - 3.f;
        if (xc >= cw) { idx++; cwlo = cw; }
        else if (!found) { cwhi = cw; found = true; }
    }
    // height knots ch[idx], ch[idx+1]
    float chlo = -TAILV, chhi = TAILV;
    float hacc = 0.f;
#pragma unroll
    for (int i = 0; i < NBINS - 1; i++) {
        hacc += MINH + sch * eh[i];
        float ch = 6.f * hacc - 3.f;
        if (i == idx - 1) chlo = ch;
        if (i == idx)     chhi = ch;
    }

    float inw = cwhi - cwlo;
    float inh = chhi - chlo;
    float delta = inh / inw;
    float ind  = (idx == 0)          ? 1.f : MIND + softplusf(p[32 + idx - 1]);
    float ind1 = (idx == NBINS - 1)  ? 1.f : MIND + softplusf(p[32 + idx]);

    float th   = (xc - cwlo) / inw;
    float omt  = 1.f - th;
    float tomt = th * omt;
    float num  = inh * (delta * th * th + ind * tomt);
    float den  = delta + (ind + ind1 - 2.f * delta) * tomt;
    float y    = chlo + num / den;
    float dnum = delta * delta * (ind1 * th * th + 2.f * delta * tomt + ind * omt * omt);
    float lad  = __logf(dnum) - 2.f * __logf(den);

    *xp = inside ? y : x;
    if (inside) atomicAdd(ldp, lad);
}

// ---------------------------------------------------------------------------
__global__ void __launch_bounds__(NT, 1)
flow_kernel(const float* __restrict__ x_in,
            const float* __restrict__ b_init,
            const float* __restrict__ b_res,
            float* __restrict__ out, int batch)
{
    extern __shared__ float sm[];
    float* xs   = sm;                      // SPB * XL
    float* hbuf = xs + SPB * XL;           // SPB * TL
    float* tbuf = hbuf + SPB * TL;         // SPB * TL
    float* ldv  = tbuf + SPB * TL;         // SPB

    int tid = threadIdx.x;
    int tx = tid & 15, ty = tid >> 4;
    int base = blockIdx.x * SPB;

    for (int i = tid; i < SPB * FF; i += NT) {
        int s = i / FF, f = i % FF;
        xs[s * XL + f] = x_in[(base + s) * FF + f];
    }
    for (int i = tid; i < SPB; i += NT) { xs[i * XL + FF] = 0.f; ldv[i] = 0.f; }
    __syncthreads();

    for (int l = 0; l < LL; l++) {
        // feature reversal
        if (tid < SPB) {
            float v[FF];
#pragma unroll
            for (int f = 0; f < FF; f++) v[f] = xs[tid * XL + f];
#pragma unroll
            for (int f = 0; f < FF; f++) xs[tid * XL + f] = v[FF - 1 - f];
        }
        __syncthreads();

        // h = xs @ Wi^T + bi   (N=128, NC=8)
        gemm2<16, 8, false, false>(xs, XL, g_Wi + l * 16 * HH, HH,
                                   b_init + l * HH, hbuf, TL, tx, ty);
        __syncthreads();

        const float* wr = g_Wr + l * 4 * HH * HH;
        const float* br = b_res + l * 4 * HH;

        gemm2<128, 8, true, false>(hbuf, TL, wr, HH, br, tbuf, TL, tx, ty);
        __syncthreads();
        gemm2<128, 8, true, true>(tbuf, TL, wr + HH * HH, HH, br + HH,
                                  hbuf, TL, tx, ty);
        __syncthreads();
        gemm2<128, 8, true, false>(hbuf, TL, wr + 2 * HH * HH, HH,
                                   br + 2 * HH, tbuf, TL, tx, ty);
        __syncthreads();
        gemm2<128, 8, true, true>(tbuf, TL, wr + 3 * HH * HH, HH,
                                  br + 3 * HH, hbuf, TL, tx, ty);
        __syncthreads();

        // output head: 8 chunks of 2 padded features (96 cols), fused RQS
        for (int c = 0; c < 8; c++) {
            gemm2<128, 6, false, false>(hbuf, TL,
                                        g_Wo + l * HH * OUTWP + c * 96, OUTWP,
                                        g_bo + l * OUTWP + c * 96,
                                        tbuf, TL, tx, ty);
            __syncthreads();
            if (tid < 2 * SPB) {
                int s = tid >> 1, q = tid & 1;
                int f = 2 * c + q;
                if (f < FF)
                    rqs_reg(&tbuf[s * TL + q * FP], &xs[s * XL + f], &ldv[s]);
            }
            __syncthreads();
        }
    }

    for (int i = tid; i < SPB * FF; i += NT) {
        int s = i / FF, f = i % FF;
        out[(base + s) * FF + f] = xs[s * XL + f];
    }
    if (tid < SPB) out[batch * FF + base + tid] = ldv[tid];
}

static const int SMEM_BYTES = (SPB * XL + 2 * SPB * TL + SPB) * (int)sizeof(float);

extern "C" void kernel_launch(void* const* d_in, const int* in_sizes, int n_in,
                              void* d_out, int out_size)
{
    const float* x  = (const float*)d_in[0];
    const float* Wi = (const float*)d_in[1];
    const float* bi = (const float*)d_in[2];
    const float* Wr = (const float*)d_in[3];
    const float* br = (const float*)d_in[4];
    const float* Wo = (const float*)d_in[5];
    const float* bo = (const float*)d_in[6];
    float* out = (float*)d_out;

    int batch = in_sizes[0] / FF;

    cudaFuncSetAttribute(flow_kernel,
                         cudaFuncAttributeMaxDynamicSharedMemorySize, SMEM_BYTES);

    prep_kernel<<<2048, 256>>>(Wi, Wr, Wo, bo);
    flow_kernel<<<batch / SPB, NT, SMEM_BYTES>>>(x, bi, br, out, batch);
}

// round 3
// speedup vs baseline: 2.0676x; 1.7630x over previous
#include <cuda_runtime.h>
#include <math.h>

#define FF 15
#define HH 128
#define LL 12
#define NBINS 16
#define MM 47            // 3*NB - 1
#define OUTW (FF*MM)     // 705
#define FP 48            // padded per-feature width
#define NFP 16           // padded feature count
#define OUTWP (NFP*FP)   // 768
#define TAILV 3.0f
#define MINW 0.001f
#define MINH 0.001f
#define MIND 0.001f
#define SPB 128          // samples per block
#define TL 132           // row stride for h/t buffers
#define XL 16            // row stride for x buffer
#define NT 256           // threads per CTA

typedef unsigned long long ull;

// Pre-masked, transposed, padded weights (scratch)
__device__ float g_Wi[LL * 16 * HH];        // [l][k(16)][j]
__device__ float g_Wr[LL * 4 * HH * HH];    // [l][blk*2+sub][k][j]
__device__ float g_Wo[LL * HH * OUTWP];     // [l][k][f*48+m]
__device__ float g_bo[LL * OUTWP];          // padded out bias

// ---------------------------------------------------------------------------
__global__ void prep_kernel(const float* __restrict__ Wi,
                            const float* __restrict__ Wr,
                            const float* __restrict__ Wo,
                            const float* __restrict__ bo)
{
    const int n1 = LL * 16 * HH;
    const int n2 = LL * 4 * HH * HH;
    const int n3 = LL * HH * OUTWP;
    const int n4 = LL * OUTWP;
    for (int i = blockIdx.x * blockDim.x + threadIdx.x; i < n1 + n2 + n3 + n4;
         i += gridDim.x * blockDim.x) {
        if (i < n1) {
            int j = i % HH;
            int k = (i / HH) % 16;
            int l = i / (16 * HH);
            float v = 0.f;
            if (k < FF) {
                int degh = j % (FF - 1) + 1;
                if (degh >= k + 1) v = Wi[(l * HH + j) * FF + k];
            }
            g_Wi[i] = v;
        } else if (i < n1 + n2) {
            int t = i - n1;
            int j = t % HH;
            int k = (t / HH) % HH;
            int m = t / (HH * HH);
            int degj = j % (FF - 1) + 1;
            int degk = k % (FF - 1) + 1;
            g_Wr[t] = (degj >= degk) ? Wr[(m * HH + j) * HH + k] : 0.f;
        } else if (i < n1 + n2 + n3) {
            int t = i - n1 - n2;
            int c = t % OUTWP;              // f*48+m
            int k = (t / OUTWP) % HH;
            int l = t / (HH * OUTWP);
            int f = c / FP, m = c % FP;
            float v = 0.f;
            if (f < FF && m < MM) {
                int degk = k % (FF - 1) + 1;
                if (f + 1 > degk) v = Wo[(l * OUTW + f * MM + m) * HH + k];
            }
            g_Wo[t] = v;
        } else {
            int t = i - n1 - n2 - n3;
            int c = t % OUTWP;
            int l = t / OUTWP;
            int f = c / FP, m = c % FP;
            g_bo[t] = (f < FF && m < MM) ? bo[l * OUTW + f * MM + m] : 0.f;
        }
    }
}

// ---------------------------------------------------------------------------
__device__ __forceinline__ void fma2(ull& d, ull a, ull b)
{
    asm("fma.rn.f32x2 %0, %1, %2, %0;" : "+l"(d) : "l"(a), "l"(b));
}
__device__ __forceinline__ ull pack2(float v)
{
    ull r; asm("mov.b64 %0, {%1, %1};" : "=l"(r) : "f"(v)); return r;
}
__device__ __forceinline__ ull packf2(float a, float b)
{
    ull r; asm("mov.b64 %0, {%1, %2};" : "=l"(r) : "f"(a), "f"(b)); return r;
}

// ---------------------------------------------------------------------------
// Weight slab load: 4 k-rows x NP ull pairs.
// VEC4: 2x LDG.128 per k-row (requires c0 16B-aligned, NP even).
// ---------------------------------------------------------------------------
template <int NP, bool VEC4>
__device__ __forceinline__ void loadW(ull (&w)[4][NP],
                                      const float* __restrict__ Wg,
                                      int wld, int c0, int k0)
{
#pragma unroll
    for (int kk = 0; kk < 4; kk++) {
        const float* wr = Wg + (k0 + kk) * wld + c0;
        if (VEC4) {
#pragma unroll
            for (int j = 0; j < NP; j += 2) {
                ulonglong2 v = __ldg((const ulonglong2*)(wr + 2 * j));
                w[kk][j] = v.x;
                w[kk][j + 1] = v.y;
            }
        } else {
#pragma unroll
            for (int j = 0; j < NP; j++)
                w[kk][j] = __ldg((const ull*)(wr + 2 * j));
        }
    }
}

// Compute one 4-wide k-chunk for 8 rows.
template <int NP, bool RELU>
__device__ __forceinline__ void computeChunk(ull (&acc)[8][NP],
                                             const float* __restrict__ As,
                                             int ald, int r0, int k0,
                                             const ull (&w)[4][NP])
{
#pragma unroll
    for (int i = 0; i < 8; i++) {
        float4 a = *(const float4*)&As[(r0 + i) * ald + k0];
        if (RELU) {
            a.x = fmaxf(a.x, 0.f);
            a.y = fmaxf(a.y, 0.f);
            a.z = fmaxf(a.z, 0.f);
            a.w = fmaxf(a.w, 0.f);
        }
        ull a0 = pack2(a.x), a1 = pack2(a.y), a2 = pack2(a.z), a3 = pack2(a.w);
#pragma unroll
        for (int j = 0; j < NP; j++) fma2(acc[i][j], a0, w[0][j]);
#pragma unroll
        for (int j = 0; j < NP; j++) fma2(acc[i][j], a1, w[1][j]);
#pragma unroll
        for (int j = 0; j < NP; j++) fma2(acc[i][j], a2, w[2][j]);
#pragma unroll
        for (int j = 0; j < NP; j++) fma2(acc[i][j], a3, w[3][j]);
    }
}

// ---------------------------------------------------------------------------
// Packed-f32x2 GEMM with double-buffered weight prefetch.
// C[128 x 16*NC] (+)= op(A[128 x K]) @ W[K x .] + bias
// 256 threads: ty = tid>>4 -> 8 rows each; tx = tid&15 -> NC cols.
// K must be a multiple of 8.
// ---------------------------------------------------------------------------
template <int K, int NC, bool VEC4, bool RELU, bool ACC>
__device__ __forceinline__ void gemm2(const float* __restrict__ As, int ald,
                                      const float* __restrict__ Wg, int wld,
                                      const float* __restrict__ bias,
                                      float* __restrict__ Cs, int cld,
                                      int tx, int ty)
{
    constexpr int NP = NC / 2;
    const int c0 = tx * NC;
    const int r0 = ty * 8;

    ull acc[8][NP];
#pragma unroll
    for (int j = 0; j < NP; j++) {
        float2 b = *(const float2*)&bias[c0 + 2 * j];
#pragma unroll
        for (int i = 0; i < 8; i++) {
            float2 p = make_float2(0.f, 0.f);
            if (ACC) p = *(const float2*)&Cs[(r0 + i) * cld + c0 + 2 * j];
            acc[i][j] = packf2(b.x + p.x, b.y + p.y);
        }
    }

    ull wa[4][NP], wb[4][NP];
    loadW<NP, VEC4>(wa, Wg, wld, c0, 0);

#pragma unroll 1
    for (int k0 = 0; k0 < K; k0 += 8) {
        loadW<NP, VEC4>(wb, Wg, wld, c0, k0 + 4);
        computeChunk<NP, RELU>(acc, As, ald, r0, k0, wa);
        if (k0 + 8 < K) loadW<NP, VEC4>(wa, Wg, wld, c0, k0 + 8);
        computeChunk<NP, RELU>(acc, As, ald, r0, k0 + 4, wb);
    }

#pragma unroll
    for (int i = 0; i < 8; i++)
#pragma unroll
        for (int j = 0; j < NP; j++)
            *(float2*)&Cs[(r0 + i) * cld + c0 + 2 * j] = *(float2*)&acc[i][j];
}

// ---------------------------------------------------------------------------
__device__ __forceinline__ float softplusf(float v)
{
    return (v > 15.f) ? v : log1pf(__expf(v));
}

// Rational-quadratic spline, register-only scratch. p = 47 raw params (smem).
__device__ void rqs_reg(const float* __restrict__ p,
                        float* __restrict__ xp, float* __restrict__ ldp)
{
    float x = *xp;
    bool inside = (x >= -TAILV) && (x <= TAILV);
    float xc = fminf(fmaxf(x, -TAILV), TAILV);

    float ew[NBINS], eh[NBINS];
    float mw = p[0], mh = p[16];
#pragma unroll
    for (int i = 1; i < NBINS; i++) { mw = fmaxf(mw, p[i]); mh = fmaxf(mh, p[16 + i]); }
    float Sw = 0.f, Sh = 0.f;
#pragma unroll
    for (int i = 0; i < NBINS; i++) {
        ew[i] = __expf(p[i] - mw);      Sw += ew[i];
        eh[i] = __expf(p[16 + i] - mh); Sh += eh[i];
    }
    float scw = (1.f - MINW * NBINS) / Sw;
    float sch = (1.f - MINH * NBINS) / Sh;

    int idx = 0;
    float cwlo = -TAILV, cwhi = TAILV;
    bool found = false;
    float cacc = 0.f;
#pragma unroll
    for (int i = 0; i < NBINS - 1; i++) {
        cacc += MINW + scw * ew[i];
        float cw = 6.f * cacc - 3.f;
        if (xc >= cw) { idx++; cwlo = cw; }
        else if (!found) { cwhi = cw; found = true; }
    }
    float chlo = -TAILV, chhi = TAILV;
    float hacc = 0.f;
#pragma unroll
    for (int i = 0; i < NBINS - 1; i++) {
        hacc += MINH + sch * eh[i];
        float ch = 6.f * hacc - 3.f;
        if (i == idx - 1) chlo = ch;
        if (i == idx)     chhi = ch;
    }

    float inw = cwhi - cwlo;
    float inh = chhi - chlo;
    float delta = inh / inw;
    float ind  = (idx == 0)          ? 1.f : MIND + softplusf(p[32 + idx - 1]);
    float ind1 = (idx == NBINS - 1)  ? 1.f : MIND + softplusf(p[32 + idx]);

    float th   = (xc - cwlo) / inw;
    float omt  = 1.f - th;
    float tomt = th * omt;
    float num  = inh * (delta * th * th + ind * tomt);
    float den  = delta + (ind + ind1 - 2.f * delta) * tomt;
    float y    = chlo + num / den;
    float dnum = delta * delta * (ind1 * th * th + 2.f * delta * tomt + ind * omt * omt);
    float lad  = __logf(dnum) - 2.f * __logf(den);

    *xp = inside ? y : x;
    if (inside) atomicAdd(ldp, lad);
}

// ---------------------------------------------------------------------------
__global__ void __launch_bounds__(NT, 1)
flow_kernel(const float* __restrict__ x_in,
            const float* __restrict__ b_init,
            const float* __restrict__ b_res,
            float* __restrict__ out, int batch)
{
    extern __shared__ float sm[];
    float* xs   = sm;                      // SPB * XL
    float* hbuf = xs + SPB * XL;           // SPB * TL
    float* tbuf = hbuf + SPB * TL;         // SPB * TL
    float* ldv  = tbuf + SPB * TL;         // SPB

    int tid = threadIdx.x;
    int tx = tid & 15, ty = tid >> 4;
    int base = blockIdx.x * SPB;

    for (int i = tid; i < SPB * FF; i += NT) {
        int s = i / FF, f = i % FF;
        xs[s * XL + f] = x_in[(base + s) * FF + f];
    }
    for (int i = tid; i < SPB; i += NT) { xs[i * XL + FF] = 0.f; ldv[i] = 0.f; }
    __syncthreads();

    for (int l = 0; l < LL; l++) {
        // feature reversal (each thread owns a full row)
        if (tid < SPB) {
            float v[FF];
#pragma unroll
            for (int f = 0; f < FF; f++) v[f] = xs[tid * XL + f];
#pragma unroll
            for (int f = 0; f < FF; f++) xs[tid * XL + f] = v[FF - 1 - f];
        }
        __syncthreads();

        // h = xs @ Wi^T + bi   (K=16, N=128, NC=8, vec4 weights)
        gemm2<16, 8, true, false, false>(xs, XL, g_Wi + l * 16 * HH, HH,
                                         b_init + l * HH, hbuf, TL, tx, ty);
        __syncthreads();

        const float* wr = g_Wr + l * 4 * HH * HH;
        const float* br = b_res + l * 4 * HH;

        gemm2<128, 8, true, true, false>(hbuf, TL, wr, HH, br, tbuf, TL, tx, ty);
        __syncthreads();
        gemm2<128, 8, true, true, true>(tbuf, TL, wr + HH * HH, HH, br + HH,
                                        hbuf, TL, tx, ty);
        __syncthreads();
        gemm2<128, 8, true, true, false>(hbuf, TL, wr + 2 * HH * HH, HH,
                                         br + 2 * HH, tbuf, TL, tx, ty);
        __syncthreads();
        gemm2<128, 8, true, true, true>(tbuf, TL, wr + 3 * HH * HH, HH,
                                        br + 3 * HH, hbuf, TL, tx, ty);
        __syncthreads();

        // output head: 8 chunks of 2 padded features (96 cols), fused RQS
        for (int c = 0; c < 8; c++) {
            gemm2<128, 6, false, false, false>(hbuf, TL,
                                               g_Wo + l * HH * OUTWP + c * 96,
                                               OUTWP,
                                               g_bo + l * OUTWP + c * 96,
                                               tbuf, TL, tx, ty);
            __syncthreads();
            {
                int s = tid >> 1, q = tid & 1;
                int f = 2 * c + q;
                if (f < FF)
                    rqs_reg(&tbuf[s * TL + q * FP], &xs[s * XL + f], &ldv[s]);
            }
            __syncthreads();
        }
    }

    for (int i = tid; i < SPB * FF; i += NT) {
        int s = i / FF, f = i % FF;
        out[(base + s) * FF + f] = xs[s * XL + f];
    }
    if (tid < SPB) out[batch * FF + base + tid] = ldv[tid];
}

static const int SMEM_BYTES = (SPB * XL + 2 * SPB * TL + SPB) * (int)sizeof(float);

extern "C" void kernel_launch(void* const* d_in, const int* in_sizes, int n_in,
                              void* d_out, int out_size)
{
    const float* x  = (const float*)d_in[0];
    const float* Wi = (const float*)d_in[1];
    const float* bi = (const float*)d_in[2];
    const float* Wr = (const float*)d_in[3];
    const float* br = (const float*)d_in[4];
    const float* Wo = (const float*)d_in[5];
    const float* bo = (const float*)d_in[6];
    float* out = (float*)d_out;

    int batch = in_sizes[0] / FF;

    cudaFuncSetAttribute(flow_kernel,
                         cudaFuncAttributeMaxDynamicSharedMemorySize, SMEM_BYTES);

    prep_kernel<<<2048, 256>>>(Wi, Wr, Wo, bo);
    flow_kernel<<<batch / SPB, NT, SMEM_BYTES>>>(x, bi, br, out, batch);
}